// round 3
// baseline (speedup 1.0000x reference)
#include <cuda_runtime.h>
#include <cuda_fp16.h>

#define NN 100000
#define NE 1600000
#define F_IN 128
#define HID 64
#define N_CLS 16

// ---------------- device scratch (allocation-free per rules) ----------------
__device__ int    g_cnt[NN];        // per-dst edge count (without self loop)
__device__ int    g_rowptr[NN];     // exclusive scan of g_cnt
__device__ int    g_cursor[NN];     // fill cursors (init to rowptr)
__device__ int    g_col[NE];        // CSR column (src) indices
__device__ float  g_dinv[NN];       // rsqrt(deg+1)
__device__ __half g_zh[NN * HID];   // dinv-scaled XW buffer (fp16)
__device__ float  g_h[NN * HID];    // hidden activations (fp32)
__device__ int    g_blksum[128];    // scan partials
__device__ int    g_is64;           // edge_index dtype flag

// packed f32x2 fma (FFMA2) — only reachable via PTX
#define FMA2(d, a, b, c) \
    asm("fma.rn.f32x2 %0, %1, %2, %3;" : "=l"(d) : "l"(a), "l"(b), "l"(c))

// ---------------- small utility kernels ----------------
__global__ void k_zero() {
    int i = blockIdx.x * blockDim.x + threadIdx.x;
    if (i < NN) g_cnt[i] = 0;
}

// Detect whether edge_index is int64 (high 32-bit words all zero) or int32.
__global__ void k_detect(const int* __restrict__ w) {
    int t = threadIdx.x;
    int nz = 0;
    for (int i = t; i < 512; i += 32) nz |= w[2 * i + 1];
    #pragma unroll
    for (int o = 16; o; o >>= 1) nz |= __shfl_xor_sync(0xffffffffu, nz, o);
    if (t == 0) g_is64 = (nz == 0) ? 1 : 0;
}

__device__ __forceinline__ int load_edge(const void* ei, long long idx) {
    if (g_is64) return (int)((const long long*)ei)[idx];
    return ((const int*)ei)[idx];
}

__global__ void k_count(const void* __restrict__ ei) {
    int i = blockIdx.x * blockDim.x + threadIdx.x;
    if (i < NE) {
        int d = load_edge(ei, (long long)NE + i);
        atomicAdd(&g_cnt[d], 1);
    }
}

// shuffle-based block scan (1024 threads)
__global__ void k_scan1() {
    __shared__ int wsum[32];
    int t = threadIdx.x, i = blockIdx.x * 1024 + t;
    int lane = t & 31, wid = t >> 5;
    int v = (i < NN) ? g_cnt[i] : 0;
    int s = v;
    #pragma unroll
    for (int o = 1; o < 32; o <<= 1) {
        int n = __shfl_up_sync(0xffffffffu, s, o);
        if (lane >= o) s += n;
    }
    if (lane == 31) wsum[wid] = s;
    __syncthreads();
    if (t < 32) {
        int w = wsum[t];
        int sc = w;
        #pragma unroll
        for (int o = 1; o < 32; o <<= 1) {
            int n = __shfl_up_sync(0xffffffffu, sc, o);
            if (t >= o) sc += n;
        }
        wsum[t] = sc - w;   // exclusive
        if (t == 31) g_blksum[blockIdx.x] = sc;   // block total
    }
    __syncthreads();
    if (i < NN) g_rowptr[i] = wsum[wid] + s - v;  // exclusive
}

__global__ void k_scan2(int nb) {
    __shared__ int s[128];
    int t = threadIdx.x;
    int v = (t < nb) ? g_blksum[t] : 0;
    s[t] = v; __syncthreads();
    #pragma unroll
    for (int off = 1; off < 128; off <<= 1) {
        int x = (t >= off) ? s[t - off] : 0;
        __syncthreads();
        s[t] += x;
        __syncthreads();
    }
    if (t < nb) g_blksum[t] = s[t] - v;
}

// finalize rowptr, seed cursors, compute dinv — fused
__global__ void k_scan3() {
    int i = blockIdx.x * blockDim.x + threadIdx.x;
    if (i < NN) {
        int rp = g_rowptr[i] + g_blksum[i >> 10];
        g_rowptr[i] = rp;
        g_cursor[i] = rp;
        g_dinv[i] = rsqrtf((float)(g_cnt[i] + 1));
    }
}

__global__ void k_fill(const void* __restrict__ ei) {
    int i = blockIdx.x * blockDim.x + threadIdx.x;
    if (i < NE) {
        int s = load_edge(ei, i);
        int d = load_edge(ei, (long long)NE + i);
        int p = atomicAdd(&g_cursor[d], 1);
        g_col[p] = s;
    }
}

// ---------------- GEMM:  Z[row,:] = half( dinv[row] * (X[row,:] @ W) ) -------
// FFMA2 (fma.rn.f32x2) with 4x4 register blocking.
// Ws in smem as plain floats (col pairs contiguous -> LDS.128 yields 2 packed b64).
// Xs in smem pre-duplicated {x,x} as b64 so broadcasts need no per-k packing.
template<int K, int COLS, int ROWS>
__global__ void k_gemm(const float* __restrict__ X, const float* __restrict__ W,
                       __half* __restrict__ Z) {
    constexpr int TDX = COLS / 4;
    constexpr int TDY = ROWS / 4;
    constexpr int NT  = TDX * TDY;
    extern __shared__ char smraw[];
    float* Ws = (float*)smraw;                                      // K*COLS f32
    unsigned long long* Xs = (unsigned long long*)(smraw + K * COLS * 4); // ROWS*K b64

    int tid  = threadIdx.x;
    int row0 = blockIdx.x * ROWS;

    for (int idx = tid; idx < K * COLS; idx += NT) Ws[idx] = W[idx];
    for (int idx = tid; idx < ROWS * K; idx += NT) {
        int r = idx / K, k = idx - r * K;
        int gr = row0 + r;
        float v = (gr < NN) ? X[(size_t)gr * K + k] : 0.f;
        unsigned long long p;
        asm("mov.b64 %0, {%1, %1};" : "=l"(p) : "r"(__float_as_uint(v)));
        Xs[idx] = p;
    }
    __syncthreads();

    int tx = tid % TDX, ty = tid / TDX;
    unsigned long long acc[4][2];
    #pragma unroll
    for (int a = 0; a < 4; a++) { acc[a][0] = 0ull; acc[a][1] = 0ull; }

    #pragma unroll 8
    for (int k = 0; k < K; k++) {
        ulonglong2 wp = *(const ulonglong2*)&Ws[k * COLS + tx * 4];
        unsigned long long x0 = Xs[(ty * 4 + 0) * K + k];
        unsigned long long x1 = Xs[(ty * 4 + 1) * K + k];
        unsigned long long x2 = Xs[(ty * 4 + 2) * K + k];
        unsigned long long x3 = Xs[(ty * 4 + 3) * K + k];
        FMA2(acc[0][0], x0, wp.x, acc[0][0]); FMA2(acc[0][1], x0, wp.y, acc[0][1]);
        FMA2(acc[1][0], x1, wp.x, acc[1][0]); FMA2(acc[1][1], x1, wp.y, acc[1][1]);
        FMA2(acc[2][0], x2, wp.x, acc[2][0]); FMA2(acc[2][1], x2, wp.y, acc[2][1]);
        FMA2(acc[3][0], x3, wp.x, acc[3][0]); FMA2(acc[3][1], x3, wp.y, acc[3][1]);
    }

    #pragma unroll
    for (int a = 0; a < 4; a++) {
        int gr = row0 + ty * 4 + a;
        if (gr < NN) {
            float d = g_dinv[gr];
            unsigned int u0, u1, u2, u3;
            asm("mov.b64 {%0, %1}, %2;" : "=r"(u0), "=r"(u1) : "l"(acc[a][0]));
            asm("mov.b64 {%0, %1}, %2;" : "=r"(u2), "=r"(u3) : "l"(acc[a][1]));
            __half2 h0 = __floats2half2_rn(__uint_as_float(u0) * d, __uint_as_float(u1) * d);
            __half2 h1 = __floats2half2_rn(__uint_as_float(u2) * d, __uint_as_float(u3) * d);
            __half2* zp = (__half2*)&Z[(size_t)gr * COLS + tx * 4];
            zp[0] = h0; zp[1] = h1;
        }
    }
}

// ---------------- aggregation:  O[i] = act(dinv[i]*(Z[i] + sum_nbr Z[src]) + b)
// warp per node; lane holds half2 (2 cols); dual accumulators for MLP.
template<bool RELU>
__global__ void k_agg64(const __half* __restrict__ Z, const float* __restrict__ bias,
                        float* __restrict__ O) {
    int w = (blockIdx.x * blockDim.x + threadIdx.x) >> 5;
    int lane = threadIdx.x & 31;
    int start = g_rowptr[w], m = g_cnt[w];

    float2 a0 = __half22float2(*(const __half2*)&Z[(size_t)w * 64 + lane * 2]); // self
    float2 a1 = make_float2(0.f, 0.f);
    for (int base = 0; base < m; base += 32) {
        int rem = m - base;
        int idx = (lane < rem) ? g_col[start + base + lane] : 0;
        int lim = rem < 32 ? rem : 32;
        int j = 0;
        for (; j + 2 <= lim; j += 2) {
            int s0 = __shfl_sync(0xffffffffu, idx, j);
            int s1 = __shfl_sync(0xffffffffu, idx, j + 1);
            float2 v0 = __half22float2(*(const __half2*)&Z[(size_t)s0 * 64 + lane * 2]);
            float2 v1 = __half22float2(*(const __half2*)&Z[(size_t)s1 * 64 + lane * 2]);
            a0.x += v0.x; a0.y += v0.y;
            a1.x += v1.x; a1.y += v1.y;
        }
        if (j < lim) {
            int s0 = __shfl_sync(0xffffffffu, idx, j);
            float2 v0 = __half22float2(*(const __half2*)&Z[(size_t)s0 * 64 + lane * 2]);
            a0.x += v0.x; a0.y += v0.y;
        }
    }
    float d  = g_dinv[w];
    float ox = fmaf(d, a0.x + a1.x, bias[lane * 2]);
    float oy = fmaf(d, a0.y + a1.y, bias[lane * 2 + 1]);
    if (RELU) { ox = fmaxf(ox, 0.f); oy = fmaxf(oy, 0.f); }
    *(float2*)&O[(size_t)w * 64 + lane * 2] = make_float2(ox, oy);
}

// 16-col final layer: 16 lanes per node, no relu, fp32 out.
__global__ void k_agg16(const __half* __restrict__ Z, const float* __restrict__ bias,
                        float* __restrict__ O) {
    int g = (blockIdx.x * blockDim.x + threadIdx.x) >> 4;
    int lane = threadIdx.x & 15;
    int start = g_rowptr[g], m = g_cnt[g];

    float a0 = __half2float(Z[(size_t)g * 16 + lane]);   // self
    float a1 = 0.f;
    for (int base = 0; base < m; base += 16) {
        int rem = m - base;
        int idx = (lane < rem) ? g_col[start + base + lane] : 0;
        int lim = rem < 16 ? rem : 16;
        int j = 0;
        for (; j + 2 <= lim; j += 2) {
            int s0 = __shfl_sync(0xffffffffu, idx, j, 16);
            int s1 = __shfl_sync(0xffffffffu, idx, j + 1, 16);
            a0 += __half2float(Z[(size_t)s0 * 16 + lane]);
            a1 += __half2float(Z[(size_t)s1 * 16 + lane]);
        }
        if (j < lim) {
            int s0 = __shfl_sync(0xffffffffu, idx, j, 16);
            a0 += __half2float(Z[(size_t)s0 * 16 + lane]);
        }
    }
    O[(size_t)g * 16 + lane] = fmaf(g_dinv[g], a0 + a1, bias[lane]);
}

// ---------------- launch ----------------
extern "C" void kernel_launch(void* const* d_in, const int* in_sizes, int n_in,
                              void* d_out, int out_size) {
    const float* x  = (const float*)d_in[0];
    const void*  ei = d_in[1];                 // int64 or int32 (detected on device)
    const float* W1 = (const float*)d_in[2];
    const float* b1 = (const float*)d_in[3];
    const float* W2 = (const float*)d_in[4];
    const float* b2 = (const float*)d_in[5];
    const float* W3 = (const float*)d_in[6];
    const float* b3 = (const float*)d_in[7];
    float* out = (float*)d_out;

    void *pz, *ph;
    cudaGetSymbolAddress(&pz, g_zh);
    cudaGetSymbolAddress(&ph, g_h);
    __half* Z = (__half*)pz;
    float*  H = (float*)ph;

    const int smem1 = F_IN * HID * 4 + 64 * F_IN * 8;    // 32768 + 65536 = 98304
    const int smem2 = HID * HID * 4 + 64 * HID * 8;      // 16384 + 32768 = 49152
    const int smem3 = HID * N_CLS * 4 + 128 * HID * 8;   //  4096 + 65536 = 69632
    cudaFuncSetAttribute(k_gemm<F_IN, HID, 64>,
                         cudaFuncAttributeMaxDynamicSharedMemorySize, smem1);
    cudaFuncSetAttribute(k_gemm<HID, HID, 64>,
                         cudaFuncAttributeMaxDynamicSharedMemorySize, smem2);
    cudaFuncSetAttribute(k_gemm<HID, N_CLS, 128>,
                         cudaFuncAttributeMaxDynamicSharedMemorySize, smem3);

    // graph structure + normalization (recomputed every call; no caching)
    k_zero<<<(NN + 255) / 256, 256>>>();
    k_detect<<<1, 32>>>((const int*)ei);
    k_count<<<(NE + 255) / 256, 256>>>(ei);
    k_scan1<<<(NN + 1023) / 1024, 1024>>>();
    k_scan2<<<1, 128>>>((NN + 1023) / 1024);
    k_scan3<<<(NN + 255) / 256, 256>>>();
    k_fill<<<(NE + 255) / 256, 256>>>(ei);

    // layer 1: 128 -> 64, relu
    k_gemm<F_IN, HID, 64><<<(NN + 63) / 64, 256, smem1>>>(x, W1, Z);
    k_agg64<true><<<(NN * 32) / 256, 256>>>(Z, b1, H);

    // layer 2: 64 -> 64, relu
    k_gemm<HID, HID, 64><<<(NN + 63) / 64, 256, smem2>>>(H, W2, Z);
    k_agg64<true><<<(NN * 32) / 256, 256>>>(Z, b2, H);

    // layer 3: 64 -> 16, no relu
    k_gemm<HID, N_CLS, 128><<<(NN + 127) / 128, 128, smem3>>>(H, W3, Z);
    k_agg16<<<(NN * 16) / 256, 256>>>(Z, b3, out);
}

// round 4
// speedup vs baseline: 1.1700x; 1.1700x over previous
#include <cuda_runtime.h>
#include <cuda_fp16.h>

#define NN 100000
#define NE 1600000
#define F_IN 128
#define HID 64
#define N_CLS 16

// ---------------- device scratch (allocation-free per rules) ----------------
__device__ int    g_cnt[NN];        // per-dst edge count (without self loop)
__device__ int    g_rowptr[NN];     // exclusive scan of g_cnt
__device__ int    g_cursor[NN];     // fill cursors (init to rowptr)
__device__ int    g_col[NE];        // CSR column (src) indices
__device__ float  g_dinv[NN];       // rsqrt(deg+1)
__device__ __half g_zh[NN * HID];   // dinv-scaled XW buffer (fp16)
__device__ float  g_h[NN * HID];    // hidden activations (fp32)
__device__ int    g_blksum[128];    // scan partials
__device__ int    g_is64;           // edge_index dtype flag

// ---------------- small utility kernels ----------------
__global__ void k_zero() {
    int i = blockIdx.x * blockDim.x + threadIdx.x;
    if (i < NN) g_cnt[i] = 0;
}

// Detect whether edge_index is int64 (high 32-bit words all zero) or int32.
__global__ void k_detect(const int* __restrict__ w) {
    int t = threadIdx.x;
    int nz = 0;
    for (int i = t; i < 512; i += 32) nz |= w[2 * i + 1];
    #pragma unroll
    for (int o = 16; o; o >>= 1) nz |= __shfl_xor_sync(0xffffffffu, nz, o);
    if (t == 0) g_is64 = (nz == 0) ? 1 : 0;
}

__device__ __forceinline__ int load_edge(const void* ei, long long idx) {
    if (g_is64) return (int)((const long long*)ei)[idx];
    return ((const int*)ei)[idx];
}

__global__ void k_count(const void* __restrict__ ei) {
    int i = blockIdx.x * blockDim.x + threadIdx.x;
    if (i < NE) {
        int d = load_edge(ei, (long long)NE + i);
        atomicAdd(&g_cnt[d], 1);
    }
}

// shuffle-based block scan (1024 threads)
__global__ void k_scan1() {
    __shared__ int wsum[32];
    int t = threadIdx.x, i = blockIdx.x * 1024 + t;
    int lane = t & 31, wid = t >> 5;
    int v = (i < NN) ? g_cnt[i] : 0;
    int s = v;
    #pragma unroll
    for (int o = 1; o < 32; o <<= 1) {
        int n = __shfl_up_sync(0xffffffffu, s, o);
        if (lane >= o) s += n;
    }
    if (lane == 31) wsum[wid] = s;
    __syncthreads();
    if (t < 32) {
        int w = wsum[t];
        int sc = w;
        #pragma unroll
        for (int o = 1; o < 32; o <<= 1) {
            int n = __shfl_up_sync(0xffffffffu, sc, o);
            if (t >= o) sc += n;
        }
        wsum[t] = sc - w;   // exclusive
        if (t == 31) g_blksum[blockIdx.x] = sc;   // block total
    }
    __syncthreads();
    if (i < NN) g_rowptr[i] = wsum[wid] + s - v;  // exclusive
}

__global__ void k_scan2(int nb) {
    __shared__ int s[128];
    int t = threadIdx.x;
    int v = (t < nb) ? g_blksum[t] : 0;
    s[t] = v; __syncthreads();
    #pragma unroll
    for (int off = 1; off < 128; off <<= 1) {
        int x = (t >= off) ? s[t - off] : 0;
        __syncthreads();
        s[t] += x;
        __syncthreads();
    }
    if (t < nb) g_blksum[t] = s[t] - v;
}

// finalize rowptr, seed cursors, compute dinv — fused
__global__ void k_scan3() {
    int i = blockIdx.x * blockDim.x + threadIdx.x;
    if (i < NN) {
        int rp = g_rowptr[i] + g_blksum[i >> 10];
        g_rowptr[i] = rp;
        g_cursor[i] = rp;
        g_dinv[i] = rsqrtf((float)(g_cnt[i] + 1));
    }
}

__global__ void k_fill(const void* __restrict__ ei) {
    int i = blockIdx.x * blockDim.x + threadIdx.x;
    if (i < NE) {
        int s = load_edge(ei, i);
        int d = load_edge(ei, (long long)NE + i);
        int p = atomicAdd(&g_cursor[d], 1);
        g_col[p] = s;
    }
}

// ---------------- GEMM:  Z[row,:] = half( dinv[row] * (X[row,:] @ W) ) -------
// R1-proven scalar-FFMA form: TM=TN=4 register blocking, X tile padded to K+1.
template<int K, int COLS, int ROWS>
__global__ void k_gemm(const float* __restrict__ X, const float* __restrict__ W,
                       __half* __restrict__ Z) {
    constexpr int TDX = COLS / 4;
    constexpr int TDY = ROWS / 4;
    constexpr int NT  = TDX * TDY;
    constexpr int KP  = K + 1;
    extern __shared__ float sm[];
    float* Ws = sm;                 // K * COLS
    float* Xs = sm + K * COLS;      // ROWS * KP

    int tid  = threadIdx.x;
    int row0 = blockIdx.x * ROWS;

    for (int idx = tid; idx < K * COLS; idx += NT) Ws[idx] = W[idx];
    for (int idx = tid; idx < ROWS * K; idx += NT) {
        int r = idx / K, k = idx - r * K;
        int gr = row0 + r;
        Xs[r * KP + k] = (gr < NN) ? X[(size_t)gr * K + k] : 0.f;
    }
    __syncthreads();

    int tx = tid % TDX, ty = tid / TDX;
    float acc[4][4];
    #pragma unroll
    for (int a = 0; a < 4; a++)
        #pragma unroll
        for (int b = 0; b < 4; b++) acc[a][b] = 0.f;

    #pragma unroll 8
    for (int k = 0; k < K; k++) {
        float4 w = *(const float4*)&Ws[k * COLS + tx * 4];
        float x0 = Xs[(ty * 4 + 0) * KP + k];
        float x1 = Xs[(ty * 4 + 1) * KP + k];
        float x2 = Xs[(ty * 4 + 2) * KP + k];
        float x3 = Xs[(ty * 4 + 3) * KP + k];
        acc[0][0] += x0 * w.x; acc[0][1] += x0 * w.y; acc[0][2] += x0 * w.z; acc[0][3] += x0 * w.w;
        acc[1][0] += x1 * w.x; acc[1][1] += x1 * w.y; acc[1][2] += x1 * w.z; acc[1][3] += x1 * w.w;
        acc[2][0] += x2 * w.x; acc[2][1] += x2 * w.y; acc[2][2] += x2 * w.z; acc[2][3] += x2 * w.w;
        acc[3][0] += x3 * w.x; acc[3][1] += x3 * w.y; acc[3][2] += x3 * w.z; acc[3][3] += x3 * w.w;
    }

    #pragma unroll
    for (int a = 0; a < 4; a++) {
        int gr = row0 + ty * 4 + a;
        if (gr < NN) {
            float d = g_dinv[gr];
            __half2 h0 = __floats2half2_rn(acc[a][0] * d, acc[a][1] * d);
            __half2 h1 = __floats2half2_rn(acc[a][2] * d, acc[a][3] * d);
            __half2* zp = (__half2*)&Z[(size_t)gr * COLS + tx * 4];
            zp[0] = h0; zp[1] = h1;
        }
    }
}

// ---------------- aggregation:  O[i] = act(dinv[i]*(Z[i] + sum_nbr Z[src]) + b)
// warp per node; lane holds half2 (2 cols); dual accumulators for MLP.
template<bool RELU>
__global__ void k_agg64(const __half* __restrict__ Z, const float* __restrict__ bias,
                        float* __restrict__ O) {
    int w = (blockIdx.x * blockDim.x + threadIdx.x) >> 5;
    int lane = threadIdx.x & 31;
    int start = g_rowptr[w], m = g_cnt[w];

    float2 a0 = __half22float2(*(const __half2*)&Z[(size_t)w * 64 + lane * 2]); // self
    float2 a1 = make_float2(0.f, 0.f);
    for (int base = 0; base < m; base += 32) {
        int rem = m - base;
        int idx = (lane < rem) ? g_col[start + base + lane] : 0;
        int lim = rem < 32 ? rem : 32;
        int j = 0;
        for (; j + 2 <= lim; j += 2) {
            int s0 = __shfl_sync(0xffffffffu, idx, j);
            int s1 = __shfl_sync(0xffffffffu, idx, j + 1);
            float2 v0 = __half22float2(*(const __half2*)&Z[(size_t)s0 * 64 + lane * 2]);
            float2 v1 = __half22float2(*(const __half2*)&Z[(size_t)s1 * 64 + lane * 2]);
            a0.x += v0.x; a0.y += v0.y;
            a1.x += v1.x; a1.y += v1.y;
        }
        if (j < lim) {
            int s0 = __shfl_sync(0xffffffffu, idx, j);
            float2 v0 = __half22float2(*(const __half2*)&Z[(size_t)s0 * 64 + lane * 2]);
            a0.x += v0.x; a0.y += v0.y;
        }
    }
    float d  = g_dinv[w];
    float ox = fmaf(d, a0.x + a1.x, bias[lane * 2]);
    float oy = fmaf(d, a0.y + a1.y, bias[lane * 2 + 1]);
    if (RELU) { ox = fmaxf(ox, 0.f); oy = fmaxf(oy, 0.f); }
    *(float2*)&O[(size_t)w * 64 + lane * 2] = make_float2(ox, oy);
}

// 16-col final layer: 16 lanes per node, no relu, fp32 out.
__global__ void k_agg16(const __half* __restrict__ Z, const float* __restrict__ bias,
                        float* __restrict__ O) {
    int g = (blockIdx.x * blockDim.x + threadIdx.x) >> 4;
    int lane = threadIdx.x & 15;
    int start = g_rowptr[g], m = g_cnt[g];

    float a0 = __half2float(Z[(size_t)g * 16 + lane]);   // self
    float a1 = 0.f;
    for (int base = 0; base < m; base += 16) {
        int rem = m - base;
        int idx = (lane < rem) ? g_col[start + base + lane] : 0;
        int lim = rem < 16 ? rem : 16;
        int j = 0;
        for (; j + 2 <= lim; j += 2) {
            int s0 = __shfl_sync(0xffffffffu, idx, j, 16);
            int s1 = __shfl_sync(0xffffffffu, idx, j + 1, 16);
            a0 += __half2float(Z[(size_t)s0 * 16 + lane]);
            a1 += __half2float(Z[(size_t)s1 * 16 + lane]);
        }
        if (j < lim) {
            int s0 = __shfl_sync(0xffffffffu, idx, j, 16);
            a0 += __half2float(Z[(size_t)s0 * 16 + lane]);
        }
    }
    O[(size_t)g * 16 + lane] = fmaf(g_dinv[g], a0 + a1, bias[lane]);
}

// ---------------- launch ----------------
extern "C" void kernel_launch(void* const* d_in, const int* in_sizes, int n_in,
                              void* d_out, int out_size) {
    const float* x  = (const float*)d_in[0];
    const void*  ei = d_in[1];                 // int64 or int32 (detected on device)
    const float* W1 = (const float*)d_in[2];
    const float* b1 = (const float*)d_in[3];
    const float* W2 = (const float*)d_in[4];
    const float* b2 = (const float*)d_in[5];
    const float* W3 = (const float*)d_in[6];
    const float* b3 = (const float*)d_in[7];
    float* out = (float*)d_out;

    void *pz, *ph;
    cudaGetSymbolAddress(&pz, g_zh);
    cudaGetSymbolAddress(&ph, g_h);
    __half* Z = (__half*)pz;
    float*  H = (float*)ph;

    const int smem1 = (F_IN * HID + 64 * (F_IN + 1)) * 4;        // 65792 B
    const int smem2 = (HID * HID + 64 * (HID + 1)) * 4;          // 33024 B
    const int smem3 = (HID * N_CLS + 128 * (HID + 1)) * 4;       // 37376 B
    cudaFuncSetAttribute(k_gemm<F_IN, HID, 64>,
                         cudaFuncAttributeMaxDynamicSharedMemorySize, smem1);

    // graph structure + normalization (recomputed every call; no caching)
    k_zero<<<(NN + 255) / 256, 256>>>();
    k_detect<<<1, 32>>>((const int*)ei);
    k_count<<<(NE + 255) / 256, 256>>>(ei);
    k_scan1<<<(NN + 1023) / 1024, 1024>>>();
    k_scan2<<<1, 128>>>((NN + 1023) / 1024);
    k_scan3<<<(NN + 255) / 256, 256>>>();
    k_fill<<<(NE + 255) / 256, 256>>>(ei);

    // layer 1: 128 -> 64, relu
    k_gemm<F_IN, HID, 64><<<(NN + 63) / 64, 256, smem1>>>(x, W1, Z);
    k_agg64<true><<<(NN * 32) / 256, 256>>>(Z, b1, H);

    // layer 2: 64 -> 64, relu
    k_gemm<HID, HID, 64><<<(NN + 63) / 64, 256, smem2>>>(H, W2, Z);
    k_agg64<true><<<(NN * 32) / 256, 256>>>(Z, b2, H);

    // layer 3: 64 -> 16, no relu
    k_gemm<HID, N_CLS, 128><<<(NN + 127) / 128, 128, smem3>>>(H, W3, Z);
    k_agg16<<<(NN * 16) / 256, 256>>>(Z, b3, out);
}

// round 5
// speedup vs baseline: 1.6740x; 1.4308x over previous
#include <cuda_runtime.h>
#include <cuda_fp16.h>

#define NN 100000
#define NE 1600000
#define F_IN 128
#define HID 64
#define N_CLS 16

// ---------------- device scratch (allocation-free per rules) ----------------
__device__ int    g_cnt[NN];
__device__ int    g_rowptr[NN];
__device__ int    g_cursor[NN];
__device__ int    g_col[NE];
__device__ float  g_dinv[NN];
__device__ __half g_zh[NN * HID];     // dinv-scaled XW (fp16)
__device__ __half g_hh[NN * HID];     // hidden activations (fp16)
__device__ __half g_wt1[HID * F_IN];  // W1^T fp16 [64][128]
__device__ __half g_wt2[HID * HID];   // W2^T fp16 [64][64]
__device__ __half g_wt3[N_CLS * HID]; // W3^T fp16 [16][64]
__device__ int    g_blksum[128];
__device__ int    g_is64;

#define LDSM4(r0, r1, r2, r3, addr) \
    asm volatile("ldmatrix.sync.aligned.m8n8.x4.shared.b16 {%0,%1,%2,%3}, [%4];" \
                 : "=r"(r0), "=r"(r1), "=r"(r2), "=r"(r3) : "r"(addr))

#define MMA16816(c, a0, a1, a2, a3, b0, b1) \
    asm volatile("mma.sync.aligned.m16n8k16.row.col.f32.f16.f16.f32 " \
                 "{%0,%1,%2,%3}, {%4,%5,%6,%7}, {%8,%9}, {%0,%1,%2,%3};" \
                 : "+f"(c[0]), "+f"(c[1]), "+f"(c[2]), "+f"(c[3]) \
                 : "r"(a0), "r"(a1), "r"(a2), "r"(a3), "r"(b0), "r"(b1))

// ---------------- small utility kernels ----------------
__global__ void k_zero() {
    int i = blockIdx.x * blockDim.x + threadIdx.x;
    if (i < NN) g_cnt[i] = 0;
}

__global__ void k_detect(const int* __restrict__ w) {
    int t = threadIdx.x;
    int nz = 0;
    for (int i = t; i < 512; i += 32) nz |= w[2 * i + 1];
    #pragma unroll
    for (int o = 16; o; o >>= 1) nz |= __shfl_xor_sync(0xffffffffu, nz, o);
    if (t == 0) g_is64 = (nz == 0) ? 1 : 0;
}

__device__ __forceinline__ int load_edge(const void* ei, long long idx) {
    if (g_is64) return (int)((const long long*)ei)[idx];
    return ((const int*)ei)[idx];
}

// transpose + fp16-convert all three weight matrices
__global__ void k_wt(const float* __restrict__ W1, const float* __restrict__ W2,
                     const float* __restrict__ W3) {
    int i = blockIdx.x * blockDim.x + threadIdx.x;
    if (i < HID * F_IN) {
        int n = i / F_IN, k = i % F_IN;
        g_wt1[n * F_IN + k] = __float2half(W1[k * HID + n]);
    } else if (i < HID * F_IN + HID * HID) {
        int j = i - HID * F_IN;
        int n = j / HID, k = j % HID;
        g_wt2[n * HID + k] = __float2half(W2[k * HID + n]);
    } else if (i < HID * F_IN + HID * HID + N_CLS * HID) {
        int j = i - HID * F_IN - HID * HID;
        int n = j / HID, k = j % HID;
        g_wt3[n * HID + k] = __float2half(W3[k * N_CLS + n]);
    }
}

__global__ void k_count(const void* __restrict__ ei) {
    int i = blockIdx.x * blockDim.x + threadIdx.x;
    if (i < NE) {
        int d = load_edge(ei, (long long)NE + i);
        atomicAdd(&g_cnt[d], 1);
    }
}

__global__ void k_scan1() {
    __shared__ int wsum[32];
    int t = threadIdx.x, i = blockIdx.x * 1024 + t;
    int lane = t & 31, wid = t >> 5;
    int v = (i < NN) ? g_cnt[i] : 0;
    int s = v;
    #pragma unroll
    for (int o = 1; o < 32; o <<= 1) {
        int n = __shfl_up_sync(0xffffffffu, s, o);
        if (lane >= o) s += n;
    }
    if (lane == 31) wsum[wid] = s;
    __syncthreads();
    if (t < 32) {
        int w = wsum[t];
        int sc = w;
        #pragma unroll
        for (int o = 1; o < 32; o <<= 1) {
            int n = __shfl_up_sync(0xffffffffu, sc, o);
            if (t >= o) sc += n;
        }
        wsum[t] = sc - w;
        if (t == 31) g_blksum[blockIdx.x] = sc;
    }
    __syncthreads();
    if (i < NN) g_rowptr[i] = wsum[wid] + s - v;
}

__global__ void k_scan2(int nb) {
    __shared__ int s[128];
    int t = threadIdx.x;
    int v = (t < nb) ? g_blksum[t] : 0;
    s[t] = v; __syncthreads();
    #pragma unroll
    for (int off = 1; off < 128; off <<= 1) {
        int x = (t >= off) ? s[t - off] : 0;
        __syncthreads();
        s[t] += x;
        __syncthreads();
    }
    if (t < nb) g_blksum[t] = s[t] - v;
}

__global__ void k_scan3() {
    int i = blockIdx.x * blockDim.x + threadIdx.x;
    if (i < NN) {
        int rp = g_rowptr[i] + g_blksum[i >> 10];
        g_rowptr[i] = rp;
        g_cursor[i] = rp;
        g_dinv[i] = rsqrtf((float)(g_cnt[i] + 1));
    }
}

__global__ void k_fill(const void* __restrict__ ei) {
    int i = blockIdx.x * blockDim.x + threadIdx.x;
    if (i < NE) {
        int s = load_edge(ei, i);
        int d = load_edge(ei, (long long)NE + i);
        int p = atomicAdd(&g_cursor[d], 1);
        g_col[p] = s;
    }
}

// ---------------- tensor-core GEMM: Z = half( dinv ⊙ (X @ W) ) --------------
// mma.sync m16n8k16, ldmatrix fragments, 128-row block tile, warp = 16 rows.
template<int K, int COLS, bool IN_HALF>
__global__ void k_mgemm(const void* __restrict__ Xv, const __half* __restrict__ Wt,
                        __half* __restrict__ Z) {
    constexpr int ROWS = 128, NT = 256, KP = K + 8, SEG = K / 8;
    constexpr int NT2 = COLS / 16;   // B ldmatrix.x4 per k-chunk
    extern __shared__ __half sh[];
    __half* Xs = sh;                 // ROWS * KP
    __half* Ws = sh + ROWS * KP;     // COLS * KP

    int tid  = threadIdx.x;
    int row0 = blockIdx.x * ROWS;

    // stage X (convert fp32 -> fp16 on the fly for layer 1)
    for (int idx = tid; idx < ROWS * SEG; idx += NT) {
        int r = idx / SEG, s = idx % SEG;
        int gr = row0 + r;
        int4 v;
        if (gr < NN) {
            if (IN_HALF) {
                v = *(const int4*)((const __half*)Xv + (size_t)gr * K + s * 8);
            } else {
                const float* xp = (const float*)Xv + (size_t)gr * K + s * 8;
                float4 f0 = *(const float4*)xp;
                float4 f1 = *(const float4*)(xp + 4);
                __half2 h0 = __floats2half2_rn(f0.x, f0.y);
                __half2 h1 = __floats2half2_rn(f0.z, f0.w);
                __half2 h2 = __floats2half2_rn(f1.x, f1.y);
                __half2 h3 = __floats2half2_rn(f1.z, f1.w);
                v.x = *(int*)&h0; v.y = *(int*)&h1; v.z = *(int*)&h2; v.w = *(int*)&h3;
            }
        } else {
            v = make_int4(0, 0, 0, 0);
        }
        *(int4*)&Xs[r * KP + s * 8] = v;
    }
    // stage W^T
    for (int idx = tid; idx < COLS * SEG; idx += NT) {
        int n = idx / SEG, s = idx % SEG;
        *(int4*)&Ws[n * KP + s * 8] = *(const int4*)&Wt[n * K + s * 8];
    }
    __syncthreads();

    int lane = tid & 31, w = tid >> 5;
    int r0   = w * 16;
    int lrow = lane & 7, grp = lane >> 3;

    float c[COLS / 8][4];
    #pragma unroll
    for (int t = 0; t < COLS / 8; t++)
        #pragma unroll
        for (int q = 0; q < 4; q++) c[t][q] = 0.f;

    // A: row offset 8*(grp&1), k offset 8*(grp>>1)
    unsigned a_base = (unsigned)__cvta_generic_to_shared(
        &Xs[(r0 + lrow + 8 * (grp & 1)) * KP + 8 * (grp >> 1)]);
    // B: n offset 8*(grp>>1), k offset 8*(grp&1)
    unsigned b_base[NT2];
    #pragma unroll
    for (int p = 0; p < NT2; p++)
        b_base[p] = (unsigned)__cvta_generic_to_shared(
            &Ws[(p * 16 + lrow + 8 * (grp >> 1)) * KP + 8 * (grp & 1)]);

    #pragma unroll
    for (int kc = 0; kc < K; kc += 16) {
        unsigned a0, a1, a2, a3;
        LDSM4(a0, a1, a2, a3, a_base + kc * 2);
        #pragma unroll
        for (int p = 0; p < NT2; p++) {
            unsigned b0, b1, b2, b3;
            LDSM4(b0, b1, b2, b3, b_base[p] + kc * 2);
            MMA16816(c[2 * p],     a0, a1, a2, a3, b0, b1);
            MMA16816(c[2 * p + 1], a0, a1, a2, a3, b2, b3);
        }
    }

    int row1 = row0 + r0 + (lane >> 2);
    int row2 = row1 + 8;
    int colp = (lane & 3) * 2;
    float d1 = (row1 < NN) ? g_dinv[row1] : 0.f;
    float d2 = (row2 < NN) ? g_dinv[row2] : 0.f;
    #pragma unroll
    for (int t = 0; t < COLS / 8; t++) {
        int col = t * 8 + colp;
        if (row1 < NN) {
            __half2 h = __floats2half2_rn(c[t][0] * d1, c[t][1] * d1);
            *(__half2*)&Z[(size_t)row1 * COLS + col] = h;
        }
        if (row2 < NN) {
            __half2 h = __floats2half2_rn(c[t][2] * d2, c[t][3] * d2);
            *(__half2*)&Z[(size_t)row2 * COLS + col] = h;
        }
    }
}

// ---------------- aggregation: O[i] = act(dinv[i]*(Z[i] + sum_nbr Z[src]) + b)
template<bool RELU>
__global__ void k_agg64(const __half* __restrict__ Z, const float* __restrict__ bias,
                        __half* __restrict__ O) {
    int w = (blockIdx.x * blockDim.x + threadIdx.x) >> 5;
    int lane = threadIdx.x & 31;
    int start = g_rowptr[w], m = g_cnt[w];

    float2 a0 = __half22float2(*(const __half2*)&Z[(size_t)w * 64 + lane * 2]); // self
    float2 a1 = make_float2(0.f, 0.f);
    for (int base = 0; base < m; base += 32) {
        int rem = m - base;
        int idx = (lane < rem) ? g_col[start + base + lane] : 0;
        int lim = rem < 32 ? rem : 32;
        int j = 0;
        for (; j + 2 <= lim; j += 2) {
            int s0 = __shfl_sync(0xffffffffu, idx, j);
            int s1 = __shfl_sync(0xffffffffu, idx, j + 1);
            float2 v0 = __half22float2(*(const __half2*)&Z[(size_t)s0 * 64 + lane * 2]);
            float2 v1 = __half22float2(*(const __half2*)&Z[(size_t)s1 * 64 + lane * 2]);
            a0.x += v0.x; a0.y += v0.y;
            a1.x += v1.x; a1.y += v1.y;
        }
        if (j < lim) {
            int s0 = __shfl_sync(0xffffffffu, idx, j);
            float2 v0 = __half22float2(*(const __half2*)&Z[(size_t)s0 * 64 + lane * 2]);
            a0.x += v0.x; a0.y += v0.y;
        }
    }
    float d  = g_dinv[w];
    float ox = fmaf(d, a0.x + a1.x, bias[lane * 2]);
    float oy = fmaf(d, a0.y + a1.y, bias[lane * 2 + 1]);
    if (RELU) { ox = fmaxf(ox, 0.f); oy = fmaxf(oy, 0.f); }
    *(__half2*)&O[(size_t)w * 64 + lane * 2] = __floats2half2_rn(ox, oy);
}

// 16-col final layer: fp32 output to d_out.
__global__ void k_agg16(const __half* __restrict__ Z, const float* __restrict__ bias,
                        float* __restrict__ O) {
    int g = (blockIdx.x * blockDim.x + threadIdx.x) >> 4;
    int lane = threadIdx.x & 15;
    int start = g_rowptr[g], m = g_cnt[g];

    float a0 = __half2float(Z[(size_t)g * 16 + lane]);   // self
    float a1 = 0.f;
    for (int base = 0; base < m; base += 16) {
        int rem = m - base;
        int idx = (lane < rem) ? g_col[start + base + lane] : 0;
        int lim = rem < 16 ? rem : 16;
        int j = 0;
        for (; j + 2 <= lim; j += 2) {
            int s0 = __shfl_sync(0xffffffffu, idx, j, 16);
            int s1 = __shfl_sync(0xffffffffu, idx, j + 1, 16);
            a0 += __half2float(Z[(size_t)s0 * 16 + lane]);
            a1 += __half2float(Z[(size_t)s1 * 16 + lane]);
        }
        if (j < lim) {
            int s0 = __shfl_sync(0xffffffffu, idx, j, 16);
            a0 += __half2float(Z[(size_t)s0 * 16 + lane]);
        }
    }
    O[(size_t)g * 16 + lane] = fmaf(g_dinv[g], a0 + a1, bias[lane]);
}

// ---------------- launch ----------------
extern "C" void kernel_launch(void* const* d_in, const int* in_sizes, int n_in,
                              void* d_out, int out_size) {
    const float* x  = (const float*)d_in[0];
    const void*  ei = d_in[1];
    const float* W1 = (const float*)d_in[2];
    const float* b1 = (const float*)d_in[3];
    const float* W2 = (const float*)d_in[4];
    const float* b2 = (const float*)d_in[5];
    const float* W3 = (const float*)d_in[6];
    const float* b3 = (const float*)d_in[7];
    float* out = (float*)d_out;

    void *pz, *ph, *pw1, *pw2, *pw3;
    cudaGetSymbolAddress(&pz, g_zh);
    cudaGetSymbolAddress(&ph, g_hh);
    cudaGetSymbolAddress(&pw1, g_wt1);
    cudaGetSymbolAddress(&pw2, g_wt2);
    cudaGetSymbolAddress(&pw3, g_wt3);
    __half* Z   = (__half*)pz;
    __half* H   = (__half*)ph;
    __half* Wt1 = (__half*)pw1;
    __half* Wt2 = (__half*)pw2;
    __half* Wt3 = (__half*)pw3;

    const int smem1 = (128 * (F_IN + 8) + HID   * (F_IN + 8)) * 2;  // 52224 B
    const int smem2 = (128 * (HID + 8)  + HID   * (HID + 8)) * 2;   // 27648 B
    const int smem3 = (128 * (HID + 8)  + N_CLS * (HID + 8)) * 2;   // 20736 B
    cudaFuncSetAttribute(k_mgemm<F_IN, HID, false>,
                         cudaFuncAttributeMaxDynamicSharedMemorySize, smem1);

    // weight prep + graph structure (recomputed every call; no caching)
    k_wt<<<(HID * F_IN + HID * HID + N_CLS * HID + 255) / 256, 256>>>(W1, W2, W3);
    k_zero<<<(NN + 255) / 256, 256>>>();
    k_detect<<<1, 32>>>((const int*)ei);
    k_count<<<(NE + 255) / 256, 256>>>(ei);
    k_scan1<<<(NN + 1023) / 1024, 1024>>>();
    k_scan2<<<1, 128>>>((NN + 1023) / 1024);
    k_scan3<<<(NN + 255) / 256, 256>>>();
    k_fill<<<(NE + 255) / 256, 256>>>(ei);

    const int gb = (NN + 127) / 128;
    // layer 1: 128 -> 64, relu
    k_mgemm<F_IN, HID, false><<<gb, 256, smem1>>>(x, Wt1, Z);
    k_agg64<true><<<(NN * 32) / 256, 256>>>(Z, b1, H);

    // layer 2: 64 -> 64, relu
    k_mgemm<HID, HID, true><<<gb, 256, smem2>>>(H, Wt2, Z);
    k_agg64<true><<<(NN * 32) / 256, 256>>>(Z, b2, H);

    // layer 3: 64 -> 16, no relu
    k_mgemm<HID, N_CLS, true><<<gb, 256, smem3>>>(H, Wt3, Z);
    k_agg16<<<(NN * 16) / 256, 256>>>(Z, b3, out);
}

// round 6
// speedup vs baseline: 1.7505x; 1.0457x over previous
#include <cuda_runtime.h>
#include <cuda_fp16.h>

#define NN 100000
#define NE 1600000
#define F_IN 128
#define HID 64
#define N_CLS 16

// ---------------- device scratch (allocation-free per rules) ----------------
__device__ int    g_cnt[NN];
__device__ int    g_rowptr[NN];
__device__ int    g_cursor[NN];
__device__ int    g_col[NE];
__device__ float  g_dinv[NN];
__device__ __half g_zh[NN * HID];     // dinv-scaled XW (fp16)
__device__ __half g_hh[NN * HID];     // hidden activations (fp16)
__device__ __half g_wt1[HID * F_IN];  // W1^T fp16 [64][128]
__device__ __half g_wt2[HID * HID];   // W2^T fp16 [64][64]
__device__ __half g_wt3[N_CLS * HID]; // W3^T fp16 [16][64]
__device__ int    g_blksum[128];
__device__ int    g_is64;

#define LDSM4(r0, r1, r2, r3, addr) \
    asm volatile("ldmatrix.sync.aligned.m8n8.x4.shared.b16 {%0,%1,%2,%3}, [%4];" \
                 : "=r"(r0), "=r"(r1), "=r"(r2), "=r"(r3) : "r"(addr))

#define MMA16816(c, a0, a1, a2, a3, b0, b1) \
    asm volatile("mma.sync.aligned.m16n8k16.row.col.f32.f16.f16.f32 " \
                 "{%0,%1,%2,%3}, {%4,%5,%6,%7}, {%8,%9}, {%0,%1,%2,%3};" \
                 : "+f"(c[0]), "+f"(c[1]), "+f"(c[2]), "+f"(c[3]) \
                 : "r"(a0), "r"(a1), "r"(a2), "r"(a3), "r"(b0), "r"(b1))

// ---------------- small utility kernels ----------------
__global__ void k_zero() {
    int i = blockIdx.x * blockDim.x + threadIdx.x;
    if (i < NN) g_cnt[i] = 0;
}

__global__ void k_detect(const int* __restrict__ w) {
    int t = threadIdx.x;
    int nz = 0;
    for (int i = t; i < 512; i += 32) nz |= w[2 * i + 1];
    #pragma unroll
    for (int o = 16; o; o >>= 1) nz |= __shfl_xor_sync(0xffffffffu, nz, o);
    if (t == 0) g_is64 = (nz == 0) ? 1 : 0;
}

__device__ __forceinline__ int load_edge(const void* ei, long long idx) {
    if (g_is64) return (int)((const long long*)ei)[idx];
    return ((const int*)ei)[idx];
}

// transpose + fp16-convert all three weight matrices
__global__ void k_wt(const float* __restrict__ W1, const float* __restrict__ W2,
                     const float* __restrict__ W3) {
    int i = blockIdx.x * blockDim.x + threadIdx.x;
    if (i < HID * F_IN) {
        int n = i / F_IN, k = i % F_IN;
        g_wt1[n * F_IN + k] = __float2half(W1[k * HID + n]);
    } else if (i < HID * F_IN + HID * HID) {
        int j = i - HID * F_IN;
        int n = j / HID, k = j % HID;
        g_wt2[n * HID + k] = __float2half(W2[k * HID + n]);
    } else if (i < HID * F_IN + HID * HID + N_CLS * HID) {
        int j = i - HID * F_IN - HID * HID;
        int n = j / HID, k = j % HID;
        g_wt3[n * HID + k] = __float2half(W3[k * N_CLS + n]);
    }
}

__global__ void k_count(const void* __restrict__ ei) {
    int i = blockIdx.x * blockDim.x + threadIdx.x;
    if (i < NE) {
        int d = load_edge(ei, (long long)NE + i);
        atomicAdd(&g_cnt[d], 1);
    }
}

__global__ void k_scan1() {
    __shared__ int wsum[32];
    int t = threadIdx.x, i = blockIdx.x * 1024 + t;
    int lane = t & 31, wid = t >> 5;
    int v = (i < NN) ? g_cnt[i] : 0;
    int s = v;
    #pragma unroll
    for (int o = 1; o < 32; o <<= 1) {
        int n = __shfl_up_sync(0xffffffffu, s, o);
        if (lane >= o) s += n;
    }
    if (lane == 31) wsum[wid] = s;
    __syncthreads();
    if (t < 32) {
        int w = wsum[t];
        int sc = w;
        #pragma unroll
        for (int o = 1; o < 32; o <<= 1) {
            int n = __shfl_up_sync(0xffffffffu, sc, o);
            if (t >= o) sc += n;
        }
        wsum[t] = sc - w;
        if (t == 31) g_blksum[blockIdx.x] = sc;
    }
    __syncthreads();
    if (i < NN) g_rowptr[i] = wsum[wid] + s - v;
}

__global__ void k_scan2(int nb) {
    __shared__ int s[128];
    int t = threadIdx.x;
    int v = (t < nb) ? g_blksum[t] : 0;
    s[t] = v; __syncthreads();
    #pragma unroll
    for (int off = 1; off < 128; off <<= 1) {
        int x = (t >= off) ? s[t - off] : 0;
        __syncthreads();
        s[t] += x;
        __syncthreads();
    }
    if (t < nb) g_blksum[t] = s[t] - v;
}

__global__ void k_scan3() {
    int i = blockIdx.x * blockDim.x + threadIdx.x;
    if (i < NN) {
        int rp = g_rowptr[i] + g_blksum[i >> 10];
        g_rowptr[i] = rp;
        g_cursor[i] = rp;
        g_dinv[i] = rsqrtf((float)(g_cnt[i] + 1));
    }
}

__global__ void k_fill(const void* __restrict__ ei) {
    int i = blockIdx.x * blockDim.x + threadIdx.x;
    if (i < NE) {
        int s = load_edge(ei, i);
        int d = load_edge(ei, (long long)NE + i);
        int p = atomicAdd(&g_cursor[d], 1);
        g_col[p] = s;
    }
}

// ---------------- tensor-core GEMM: Z = half( dinv ⊙ (X @ W) ) --------------
template<int K, int COLS, bool IN_HALF>
__global__ void k_mgemm(const void* __restrict__ Xv, const __half* __restrict__ Wt,
                        __half* __restrict__ Z) {
    constexpr int ROWS = 128, NT = 256, KP = K + 8, SEG = K / 8;
    constexpr int NT2 = COLS / 16;
    extern __shared__ __half sh[];
    __half* Xs = sh;                 // ROWS * KP
    __half* Ws = sh + ROWS * KP;     // COLS * KP

    int tid  = threadIdx.x;
    int row0 = blockIdx.x * ROWS;

    for (int idx = tid; idx < ROWS * SEG; idx += NT) {
        int r = idx / SEG, s = idx % SEG;
        int gr = row0 + r;
        int4 v;
        if (gr < NN) {
            if (IN_HALF) {
                v = *(const int4*)((const __half*)Xv + (size_t)gr * K + s * 8);
            } else {
                const float* xp = (const float*)Xv + (size_t)gr * K + s * 8;
                float4 f0 = *(const float4*)xp;
                float4 f1 = *(const float4*)(xp + 4);
                __half2 h0 = __floats2half2_rn(f0.x, f0.y);
                __half2 h1 = __floats2half2_rn(f0.z, f0.w);
                __half2 h2 = __floats2half2_rn(f1.x, f1.y);
                __half2 h3 = __floats2half2_rn(f1.z, f1.w);
                v.x = *(int*)&h0; v.y = *(int*)&h1; v.z = *(int*)&h2; v.w = *(int*)&h3;
            }
        } else {
            v = make_int4(0, 0, 0, 0);
        }
        *(int4*)&Xs[r * KP + s * 8] = v;
    }
    for (int idx = tid; idx < COLS * SEG; idx += NT) {
        int n = idx / SEG, s = idx % SEG;
        *(int4*)&Ws[n * KP + s * 8] = *(const int4*)&Wt[n * K + s * 8];
    }
    __syncthreads();

    int lane = tid & 31, w = tid >> 5;
    int r0   = w * 16;
    int lrow = lane & 7, grp = lane >> 3;

    float c[COLS / 8][4];
    #pragma unroll
    for (int t = 0; t < COLS / 8; t++)
        #pragma unroll
        for (int q = 0; q < 4; q++) c[t][q] = 0.f;

    unsigned a_base = (unsigned)__cvta_generic_to_shared(
        &Xs[(r0 + lrow + 8 * (grp & 1)) * KP + 8 * (grp >> 1)]);
    unsigned b_base[NT2];
    #pragma unroll
    for (int p = 0; p < NT2; p++)
        b_base[p] = (unsigned)__cvta_generic_to_shared(
            &Ws[(p * 16 + lrow + 8 * (grp >> 1)) * KP + 8 * (grp & 1)]);

    #pragma unroll
    for (int kc = 0; kc < K; kc += 16) {
        unsigned a0, a1, a2, a3;
        LDSM4(a0, a1, a2, a3, a_base + kc * 2);
        #pragma unroll
        for (int p = 0; p < NT2; p++) {
            unsigned b0, b1, b2, b3;
            LDSM4(b0, b1, b2, b3, b_base[p] + kc * 2);
            MMA16816(c[2 * p],     a0, a1, a2, a3, b0, b1);
            MMA16816(c[2 * p + 1], a0, a1, a2, a3, b2, b3);
        }
    }

    int row1 = row0 + r0 + (lane >> 2);
    int row2 = row1 + 8;
    int colp = (lane & 3) * 2;
    float d1 = (row1 < NN) ? g_dinv[row1] : 0.f;
    float d2 = (row2 < NN) ? g_dinv[row2] : 0.f;
    #pragma unroll
    for (int t = 0; t < COLS / 8; t++) {
        int col = t * 8 + colp;
        if (row1 < NN) {
            __half2 h = __floats2half2_rn(c[t][0] * d1, c[t][1] * d1);
            *(__half2*)&Z[(size_t)row1 * COLS + col] = h;
        }
        if (row2 < NN) {
            __half2 h = __floats2half2_rn(c[t][2] * d2, c[t][3] * d2);
            *(__half2*)&Z[(size_t)row2 * COLS + col] = h;
        }
    }
}

// ---------------- aggregation: O[i] = act(dinv[i]*(Z[i] + sum_nbr Z[src]) + b)
// warp per node; 4 groups of 8 lanes, each group handles one edge per step;
// lane loads int4 (8 halfs). One LDG.128 instruction covers 4 edges (512B).
template<bool RELU>
__global__ void k_agg64(const __half* __restrict__ Z, const float* __restrict__ bias,
                        __half* __restrict__ O) {
    int w = (blockIdx.x * blockDim.x + threadIdx.x) >> 5;
    int lane = threadIdx.x & 31;
    int grp = lane >> 3;          // edge group 0..3
    int sub = lane & 7;           // column octet 0..7
    int start = g_rowptr[w], m = g_cnt[w];

    float acc[8];
    if (grp == 0) {               // self loop handled by group 0
        int4 v = *(const int4*)&Z[(size_t)w * 64 + sub * 8];
        __half2* h = (__half2*)&v;
        #pragma unroll
        for (int q = 0; q < 4; q++) {
            float2 f = __half22float2(h[q]);
            acc[2 * q] = f.x; acc[2 * q + 1] = f.y;
        }
    } else {
        #pragma unroll
        for (int q = 0; q < 8; q++) acc[q] = 0.f;
    }

    for (int base = 0; base < m; base += 32) {
        int rem = m - base;
        int idx = (lane < rem) ? g_col[start + base + lane] : 0;
        int lim = rem < 32 ? rem : 32;
        for (int j = 0; j < lim; j += 4) {
            int e = j + grp;
            int s = __shfl_sync(0xffffffffu, idx, e & 31);
            if (e < lim) {
                int4 v = *(const int4*)&Z[(size_t)s * 64 + sub * 8];
                __half2* h = (__half2*)&v;
                #pragma unroll
                for (int q = 0; q < 4; q++) {
                    float2 f = __half22float2(h[q]);
                    acc[2 * q] += f.x; acc[2 * q + 1] += f.y;
                }
            }
        }
    }
    // combine the 4 edge groups
    #pragma unroll
    for (int q = 0; q < 8; q++) {
        acc[q] += __shfl_xor_sync(0xffffffffu, acc[q], 8);
        acc[q] += __shfl_xor_sync(0xffffffffu, acc[q], 16);
    }
    if (grp == 0) {
        float d = g_dinv[w];
        __half2 hv[4];
        #pragma unroll
        for (int q = 0; q < 4; q++) {
            float ox = fmaf(d, acc[2 * q],     bias[sub * 8 + 2 * q]);
            float oy = fmaf(d, acc[2 * q + 1], bias[sub * 8 + 2 * q + 1]);
            if (RELU) { ox = fmaxf(ox, 0.f); oy = fmaxf(oy, 0.f); }
            hv[q] = __floats2half2_rn(ox, oy);
        }
        *(int4*)&O[(size_t)w * 64 + sub * 8] = *(int4*)hv;
    }
}

// 16-col final layer: warp per node; 16 groups of 2 lanes, 16 edges per step.
__global__ void k_agg16(const __half* __restrict__ Z, const float* __restrict__ bias,
                        float* __restrict__ O) {
    int w = (blockIdx.x * blockDim.x + threadIdx.x) >> 5;
    int lane = threadIdx.x & 31;
    int grp = lane >> 1;          // edge group 0..15
    int sub = lane & 1;           // column octet 0..1
    int start = g_rowptr[w], m = g_cnt[w];

    float acc[8];
    if (grp == 0) {               // self loop
        int4 v = *(const int4*)&Z[(size_t)w * 16 + sub * 8];
        __half2* h = (__half2*)&v;
        #pragma unroll
        for (int q = 0; q < 4; q++) {
            float2 f = __half22float2(h[q]);
            acc[2 * q] = f.x; acc[2 * q + 1] = f.y;
        }
    } else {
        #pragma unroll
        for (int q = 0; q < 8; q++) acc[q] = 0.f;
    }

    for (int base = 0; base < m; base += 32) {
        int rem = m - base;
        int idx = (lane < rem) ? g_col[start + base + lane] : 0;
        int lim = rem < 32 ? rem : 32;
        for (int j = 0; j < lim; j += 16) {
            int e = j + grp;
            int s = __shfl_sync(0xffffffffu, idx, e & 31);
            if (e < lim) {
                int4 v = *(const int4*)&Z[(size_t)s * 16 + sub * 8];
                __half2* h = (__half2*)&v;
                #pragma unroll
                for (int q = 0; q < 4; q++) {
                    float2 f = __half22float2(h[q]);
                    acc[2 * q] += f.x; acc[2 * q + 1] += f.y;
                }
            }
        }
    }
    // combine 16 edge groups
    #pragma unroll
    for (int q = 0; q < 8; q++) {
        acc[q] += __shfl_xor_sync(0xffffffffu, acc[q], 2);
        acc[q] += __shfl_xor_sync(0xffffffffu, acc[q], 4);
        acc[q] += __shfl_xor_sync(0xffffffffu, acc[q], 8);
        acc[q] += __shfl_xor_sync(0xffffffffu, acc[q], 16);
    }
    if (grp == 0) {
        float d = g_dinv[w];
        float o[8];
        #pragma unroll
        for (int q = 0; q < 8; q++) o[q] = fmaf(d, acc[q], bias[sub * 8 + q]);
        float4* op = (float4*)&O[(size_t)w * 16 + sub * 8];
        op[0] = make_float4(o[0], o[1], o[2], o[3]);
        op[1] = make_float4(o[4], o[5], o[6], o[7]);
    }
}

// ---------------- launch ----------------
extern "C" void kernel_launch(void* const* d_in, const int* in_sizes, int n_in,
                              void* d_out, int out_size) {
    const float* x  = (const float*)d_in[0];
    const void*  ei = d_in[1];
    const float* W1 = (const float*)d_in[2];
    const float* b1 = (const float*)d_in[3];
    const float* W2 = (const float*)d_in[4];
    const float* b2 = (const float*)d_in[5];
    const float* W3 = (const float*)d_in[6];
    const float* b3 = (const float*)d_in[7];
    float* out = (float*)d_out;

    void *pz, *ph, *pw1, *pw2, *pw3;
    cudaGetSymbolAddress(&pz, g_zh);
    cudaGetSymbolAddress(&ph, g_hh);
    cudaGetSymbolAddress(&pw1, g_wt1);
    cudaGetSymbolAddress(&pw2, g_wt2);
    cudaGetSymbolAddress(&pw3, g_wt3);
    __half* Z   = (__half*)pz;
    __half* H   = (__half*)ph;
    __half* Wt1 = (__half*)pw1;
    __half* Wt2 = (__half*)pw2;
    __half* Wt3 = (__half*)pw3;

    const int smem1 = (128 * (F_IN + 8) + HID   * (F_IN + 8)) * 2;  // 52224 B
    const int smem2 = (128 * (HID + 8)  + HID   * (HID + 8)) * 2;   // 27648 B
    const int smem3 = (128 * (HID + 8)  + N_CLS * (HID + 8)) * 2;   // 20736 B
    cudaFuncSetAttribute(k_mgemm<F_IN, HID, false>,
                         cudaFuncAttributeMaxDynamicSharedMemorySize, smem1);

    // weight prep + graph structure (recomputed every call; no caching)
    k_wt<<<(HID * F_IN + HID * HID + N_CLS * HID + 255) / 256, 256>>>(W1, W2, W3);
    k_zero<<<(NN + 255) / 256, 256>>>();
    k_detect<<<1, 32>>>((const int*)ei);
    k_count<<<(NE + 255) / 256, 256>>>(ei);
    k_scan1<<<(NN + 1023) / 1024, 1024>>>();
    k_scan2<<<1, 128>>>((NN + 1023) / 1024);
    k_scan3<<<(NN + 255) / 256, 256>>>();
    k_fill<<<(NE + 255) / 256, 256>>>(ei);

    const int gb = (NN + 127) / 128;
    // layer 1: 128 -> 64, relu
    k_mgemm<F_IN, HID, false><<<gb, 256, smem1>>>(x, Wt1, Z);
    k_agg64<true><<<(NN * 32) / 256, 256>>>(Z, b1, H);

    // layer 2: 64 -> 64, relu
    k_mgemm<HID, HID, true><<<gb, 256, smem2>>>(H, Wt2, Z);
    k_agg64<true><<<(NN * 32) / 256, 256>>>(Z, b2, H);

    // layer 3: 64 -> 16, no relu
    k_mgemm<HID, N_CLS, true><<<gb, 256, smem3>>>(H, Wt3, Z);
    k_agg16<<<(NN * 32) / 256, 256>>>(Z, b3, out);
}